// round 1
// baseline (speedup 1.0000x reference)
#include <cuda_runtime.h>

#define NN 20000
#define NE 320000
#define DD 256
#define LGC 4
#define KCH 768
#define KCL 1024
#define BN_EPS 1e-5f

// ---------------- scratch (static __device__, no allocation) ----------------
__device__ float g_deg[NN];
__device__ float g_dis[NN];
__device__ float g_norm[NE];
__device__ int   g_cnt[NN];
__device__ int   g_cur[NN];
__device__ int   g_ptr[NN + 1];
__device__ int   g_eid[NE];
__device__ int   g_src[NE];
__device__ float g_w[NE];
__device__ float g_tcat[(size_t)NN * KCH];   // [N, 768] = [T0 | T1 | T2]
__device__ float g_h[(size_t)NN * DD];       // layer output [N, 256]
__device__ float g_jk[(size_t)NN * 1024];    // JK concat [N, 1024]
__device__ float g_z[(size_t)NN * DD];       // classifier hidden [N, 256]

// ---------------- setup kernels ----------------
__global__ void k_zero() {
    int i = blockIdx.x * blockDim.x + threadIdx.x;
    if (i < NN) { g_deg[i] = 0.f; g_cnt[i] = 0; g_cur[i] = 0; }
}

__global__ void k_deg(const int* __restrict__ row, const float* __restrict__ ew) {
    int e = blockIdx.x * blockDim.x + threadIdx.x;
    if (e < NE) atomicAdd(&g_deg[row[e]], ew[e]);
}

__global__ void k_dis() {
    int i = blockIdx.x * blockDim.x + threadIdx.x;
    if (i < NN) {
        float d = g_deg[i];
        float y = 0.f;
        if (d > 0.f) {
            y = rsqrtf(d);
            y = y * (1.5f - 0.5f * d * y * y);  // Newton refine
        }
        g_dis[i] = y;
    }
}

__global__ void k_norm(const int* __restrict__ row, const int* __restrict__ col,
                       const float* __restrict__ ew, float* __restrict__ out_ew) {
    int e = blockIdx.x * blockDim.x + threadIdx.x;
    if (e < NE) {
        float w = ew[e];
        g_norm[e] = -(g_dis[row[e]] * w * g_dis[col[e]]);
        atomicAdd(&g_cnt[col[e]], 1);
        out_ew[e] = w;
    }
}

// exclusive prefix sum of g_cnt -> g_ptr (single block, 1024 threads)
__global__ void k_scan() {
    __shared__ int sh[1024];
    const int CH = 20;  // 1024*20 >= 20000
    int tid = threadIdx.x;
    int base = tid * CH;
    int s = 0;
    for (int i = 0; i < CH; i++) {
        int idx = base + i;
        if (idx < NN) s += g_cnt[idx];
    }
    sh[tid] = s;
    __syncthreads();
    // inclusive Hillis-Steele scan
    for (int off = 1; off < 1024; off <<= 1) {
        int v = (tid >= off) ? sh[tid - off] : 0;
        __syncthreads();
        sh[tid] += v;
        __syncthreads();
    }
    int run = (tid == 0) ? 0 : sh[tid - 1];
    for (int i = 0; i < CH; i++) {
        int idx = base + i;
        if (idx < NN) { g_ptr[idx] = run; run += g_cnt[idx]; }
    }
    if (tid == 1023) g_ptr[NN] = sh[1023];
}

__global__ void k_scatter(const int* __restrict__ col) {
    int e = blockIdx.x * blockDim.x + threadIdx.x;
    if (e < NE) {
        int c = col[e];
        int pos = g_ptr[c] + atomicAdd(&g_cur[c], 1);
        g_eid[pos] = e;
    }
}

// canonicalize per-node edge order (deterministic) + build gather arrays
__global__ void k_sortfill(const int* __restrict__ row) {
    int c = blockIdx.x * blockDim.x + threadIdx.x;
    if (c >= NN) return;
    int b = g_ptr[c], t = g_ptr[c + 1];
    for (int i = b + 1; i < t; i++) {
        int v = g_eid[i];
        int j = i - 1;
        while (j >= b && g_eid[j] > v) { g_eid[j + 1] = g_eid[j]; j--; }
        g_eid[j + 1] = v;
    }
    for (int p = b; p < t; p++) {
        int e = g_eid[p];
        g_src[p] = row[e];
        g_w[p] = g_norm[e];
    }
}

// ---------------- cheb propagation ----------------
// copy T0 = x into g_tcat[:, 0:256]
__global__ void k_copyT0(const float* __restrict__ feat, int use_feat) {
    int i = blockIdx.x * blockDim.x + threadIdx.x;
    if (i >= NN * DD) return;
    int n = i >> 8, d = i & 255;
    float v = use_feat ? feat[i] : g_h[i];
    g_tcat[(size_t)n * KCH + d] = v;
}

// phase 0: T1 = prop(x)           -> g_tcat[:, 256:512]
// phase 1: T2 = 2*prop(T1) - x    -> g_tcat[:, 512:768]
__global__ void k_prop(const float* __restrict__ feat, int use_feat, int phase) {
    int c = blockIdx.x;         // node
    int t = threadIdx.x;        // 128 threads, float2 each
    const float* xbase;
    int stride;
    if (phase == 0) { xbase = use_feat ? feat : g_h; stride = 256; }
    else            { xbase = g_tcat + 256;          stride = KCH; }

    float2 acc = make_float2(0.f, 0.f);
    int b = g_ptr[c], e = g_ptr[c + 1];
    for (int p = b; p < e; p++) {
        float w = g_w[p];
        int s = g_src[p];
        float2 v = *(const float2*)(xbase + (size_t)s * stride + 2 * t);
        acc.x += w * v.x;
        acc.y += w * v.y;
    }
    if (phase == 0) {
        *(float2*)(g_tcat + (size_t)c * KCH + 256 + 2 * t) = acc;
    } else {
        const float* x0 = use_feat ? feat : g_h;
        float2 v0 = *(const float2*)(x0 + (size_t)c * 256 + 2 * t);
        acc.x = 2.f * acc.x - v0.x;
        acc.y = 2.f * acc.y - v0.y;
        *(float2*)(g_tcat + (size_t)c * KCH + 512 + 2 * t) = acc;
    }
}

// ---------------- tiled fp32 GEMM ----------------
// C[M=NN, 256] = A[M,K] @ B[K,256] + epilogue
// EPI 0: A=g_tcat, relu -> g_h and g_jk[:, jkoff:jkoff+256]
// EPI 1: A=g_jk,  +bias, relu, BN -> g_z
template <int EPI>
__global__ void __launch_bounds__(256, 2)
k_gemm(int K, const float* __restrict__ B,
       const float* __restrict__ bias, const float* __restrict__ gamma,
       const float* __restrict__ beta, const float* __restrict__ mean,
       const float* __restrict__ var, int jkoff) {
    const float* A = (EPI == 0) ? g_tcat : g_jk;
    __shared__ float As[16][132];  // transposed, padded
    __shared__ float Bs[16][128];

    int tid = threadIdx.x;
    int brow = blockIdx.y * 128;
    int bcol = blockIdx.x * 128;
    int tx = tid & 15, ty = tid >> 4;

    int ar = tid >> 2;          // 0..63 (+64)
    int ac = (tid & 3) * 4;     // k offset within tile
    int br = tid >> 5;          // 0..7 (+8)
    int bc = (tid & 31) * 4;

    float acc[8][8];
#pragma unroll
    for (int i = 0; i < 8; i++)
#pragma unroll
        for (int j = 0; j < 8; j++) acc[i][j] = 0.f;

    float4 aReg[2], bReg[2];
    int nk = K >> 4;

    auto loadA = [&](int kt) {
#pragma unroll
        for (int i = 0; i < 2; i++) {
            int r = brow + ar + i * 64;
            int kk = kt * 16 + ac;
            if (r < NN) aReg[i] = *(const float4*)(A + (size_t)r * K + kk);
            else        aReg[i] = make_float4(0.f, 0.f, 0.f, 0.f);
        }
    };
    auto loadB = [&](int kt) {
#pragma unroll
        for (int i = 0; i < 2; i++) {
            int kk = kt * 16 + br + i * 8;
            bReg[i] = *(const float4*)(B + (size_t)kk * 256 + bcol + bc);
        }
    };
    auto storeAB = [&]() {
#pragma unroll
        for (int i = 0; i < 2; i++) {
            As[ac + 0][ar + i * 64] = aReg[i].x;
            As[ac + 1][ar + i * 64] = aReg[i].y;
            As[ac + 2][ar + i * 64] = aReg[i].z;
            As[ac + 3][ar + i * 64] = aReg[i].w;
            *(float4*)&Bs[br + i * 8][bc] = bReg[i];
        }
    };

    loadA(0); loadB(0);
    storeAB();
    __syncthreads();

    for (int kt = 0; kt < nk; kt++) {
        if (kt + 1 < nk) { loadA(kt + 1); loadB(kt + 1); }
#pragma unroll
        for (int k = 0; k < 16; k++) {
            float ra[8], rb[8];
            *(float4*)&ra[0] = *(const float4*)&As[k][ty * 8];
            *(float4*)&ra[4] = *(const float4*)&As[k][ty * 8 + 4];
            *(float4*)&rb[0] = *(const float4*)&Bs[k][tx * 8];
            *(float4*)&rb[4] = *(const float4*)&Bs[k][tx * 8 + 4];
#pragma unroll
            for (int i = 0; i < 8; i++)
#pragma unroll
                for (int j = 0; j < 8; j++) acc[i][j] += ra[i] * rb[j];
        }
        __syncthreads();
        if (kt + 1 < nk) {
            storeAB();
            __syncthreads();
        }
    }

#pragma unroll
    for (int i = 0; i < 8; i++) {
        int r = brow + ty * 8 + i;
        if (r >= NN) continue;
#pragma unroll
        for (int jj = 0; jj < 2; jj++) {
            int col0 = bcol + tx * 8 + jj * 4;
            float4 v;
            float* a = &acc[i][jj * 4];
            if (EPI == 0) {
                v.x = fmaxf(a[0], 0.f); v.y = fmaxf(a[1], 0.f);
                v.z = fmaxf(a[2], 0.f); v.w = fmaxf(a[3], 0.f);
                *(float4*)(g_h + (size_t)r * 256 + col0) = v;
                *(float4*)(g_jk + (size_t)r * 1024 + jkoff + col0) = v;
            } else {
                float o[4];
#pragma unroll
                for (int q = 0; q < 4; q++) {
                    int cc = col0 + q;
                    float t = fmaxf(a[q] + bias[cc], 0.f);
                    float s = gamma[cc] * rsqrtf(var[cc] + BN_EPS);
                    o[q] = (t - mean[cc]) * s + beta[cc];
                }
                v.x = o[0]; v.y = o[1]; v.z = o[2]; v.w = o[3];
                *(float4*)(g_z + (size_t)r * 256 + col0) = v;
            }
        }
    }
}

// ---------------- final projection [256] -> [2], one warp per node ----------------
__global__ void k_logit(const float* __restrict__ w2, const float* __restrict__ b2,
                        float* __restrict__ out) {
    int gw = (blockIdx.x * blockDim.x + threadIdx.x) >> 5;
    int lane = threadIdx.x & 31;
    if (gw >= NN) return;
    const float* z = g_z + (size_t)gw * 256;
    float a0 = 0.f, a1 = 0.f;
#pragma unroll
    for (int i = lane; i < 256; i += 32) {
        float zv = z[i];
        a0 += zv * w2[i * 2];
        a1 += zv * w2[i * 2 + 1];
    }
#pragma unroll
    for (int off = 16; off; off >>= 1) {
        a0 += __shfl_down_sync(0xffffffffu, a0, off);
        a1 += __shfl_down_sync(0xffffffffu, a1, off);
    }
    if (lane == 0) {
        out[gw * 2 + 0] = a0 + b2[0];
        out[gw * 2 + 1] = a1 + b2[1];
    }
}

// ---------------- launch ----------------
extern "C" void kernel_launch(void* const* d_in, const int* in_sizes, int n_in,
                              void* d_out, int out_size) {
    const float* features = (const float*)d_in[0];
    const int*   eidx     = (const int*)d_in[1];
    const float* ew       = (const float*)d_in[3];   // d_in[2] edgenet_input unused (eval)
    const float* cheb_w   = (const float*)d_in[4];
    const float* w1       = (const float*)d_in[5];
    const float* b1       = (const float*)d_in[6];
    const float* gamma    = (const float*)d_in[7];
    const float* beta     = (const float*)d_in[8];
    const float* mean     = (const float*)d_in[9];
    const float* var      = (const float*)d_in[10];
    const float* w2       = (const float*)d_in[11];
    const float* b2       = (const float*)d_in[12];

    const int* row = eidx;
    const int* col = eidx + NE;
    float* out_logit = (float*)d_out;
    float* out_ew    = (float*)d_out + NN * 2;

    // graph normalization + CSC build
    k_zero<<<(NN + 255) / 256, 256>>>();
    k_deg<<<(NE + 255) / 256, 256>>>(row, ew);
    k_dis<<<(NN + 255) / 256, 256>>>();
    k_norm<<<(NE + 255) / 256, 256>>>(row, col, ew, out_ew);
    k_scan<<<1, 1024>>>();
    k_scatter<<<(NE + 255) / 256, 256>>>(col);
    k_sortfill<<<(NN + 127) / 128, 128>>>(row);

    dim3 ggrid(2, (NN + 127) / 128);
    for (int l = 0; l < LGC; l++) {
        int use_feat = (l == 0) ? 1 : 0;
        k_copyT0<<<(NN * DD + 255) / 256, 256>>>(features, use_feat);
        k_prop<<<NN, 128>>>(features, use_feat, 0);
        k_prop<<<NN, 128>>>(features, use_feat, 1);
        k_gemm<0><<<ggrid, 256>>>(KCH, cheb_w + (size_t)l * 3 * 256 * 256,
                                  nullptr, nullptr, nullptr, nullptr, nullptr, l * 256);
    }

    k_gemm<1><<<ggrid, 256>>>(KCL, w1, b1, gamma, beta, mean, var, 0);
    k_logit<<<(NN * 32 + 255) / 256, 256>>>(w2, b2, out_logit);
}

// round 8
// speedup vs baseline: 1.7095x; 1.7095x over previous
#include <cuda_runtime.h>
#include <cuda_bf16.h>
#include <cstdint>

#define NN 20000
#define NE 320000
#define DD 256
#define LGC 4
#define KCH 768
#define KCL 1024
#define BN_EPS 1e-5f

// ==================== scratch ====================
__device__ float g_deg[NN];
__device__ float g_dis[NN];
__device__ float g_norm[NE];
__device__ int   g_cnt[NN];
__device__ int   g_cur[NN];
__device__ int   g_ptr[NN + 1];
__device__ int   g_eid[NE];
__device__ int   g_src[NE];
__device__ float g_w[NE];
__device__ float g_tcat[(size_t)NN * KCH];   // [N, 768] = [T0 | T1 | T2]
__device__ float g_h[(size_t)NN * DD];       // layer output (relu)
__device__ float g_jk[(size_t)NN * 1024];    // JK concat [N, 1024]
__device__ float g_z[(size_t)NN * DD];       // classifier hidden [N, 256]
// transposed bf16 hi/lo weights: [256 n][K/2 kpairs] as uint32 (bf16x2, low half = even k)
__device__ uint32_t g_wch_hi[LGC * 256 * (KCH / 2)];
__device__ uint32_t g_wch_lo[LGC * 256 * (KCH / 2)];
__device__ uint32_t g_wcl_hi[256 * (KCL / 2)];
__device__ uint32_t g_wcl_lo[256 * (KCL / 2)];

__device__ __forceinline__ uint32_t packbf(__nv_bfloat16 a, __nv_bfloat16 b) {
    return (uint32_t)__bfloat16_as_ushort(a) | ((uint32_t)__bfloat16_as_ushort(b) << 16);
}

__device__ __forceinline__ uint32_t smem_u32(const void* p) {
    uint32_t a;
    asm("{ .reg .u64 t; cvta.to.shared.u64 t, %1; cvt.u32.u64 %0, t; }" : "=r"(a) : "l"(p));
    return a;
}

__device__ __forceinline__ void ldm_x4(uint32_t r[4], uint32_t addr) {
    asm volatile("ldmatrix.sync.aligned.m8n8.x4.shared.b16 {%0,%1,%2,%3}, [%4];"
                 : "=r"(r[0]), "=r"(r[1]), "=r"(r[2]), "=r"(r[3]) : "r"(addr));
}

__device__ __forceinline__ void mma16816(float c[4], const uint32_t a[4], const uint32_t b0,
                                         const uint32_t b1) {
    asm volatile(
        "mma.sync.aligned.m16n8k16.row.col.f32.bf16.bf16.f32 "
        "{%0,%1,%2,%3}, {%4,%5,%6,%7}, {%8,%9}, {%0,%1,%2,%3};"
        : "+f"(c[0]), "+f"(c[1]), "+f"(c[2]), "+f"(c[3])
        : "r"(a[0]), "r"(a[1]), "r"(a[2]), "r"(a[3]), "r"(b0), "r"(b1));
}

// ==================== setup kernels ====================
__global__ void k_zero() {
    int i = blockIdx.x * blockDim.x + threadIdx.x;
    if (i < NN) { g_deg[i] = 0.f; g_cnt[i] = 0; g_cur[i] = 0; }
}

__global__ void k_deg(const int* __restrict__ row, const float* __restrict__ ew) {
    int e = blockIdx.x * blockDim.x + threadIdx.x;
    if (e < NE) atomicAdd(&g_deg[row[e]], ew[e]);
}

__global__ void k_dis() {
    int i = blockIdx.x * blockDim.x + threadIdx.x;
    if (i < NN) {
        float d = g_deg[i];
        float y = 0.f;
        if (d > 0.f) {
            y = rsqrtf(d);
            y = y * (1.5f - 0.5f * d * y * y);  // Newton refine
        }
        g_dis[i] = y;
    }
}

__global__ void k_norm(const int* __restrict__ row, const int* __restrict__ col,
                       const float* __restrict__ ew, float* __restrict__ out_ew) {
    int e = blockIdx.x * blockDim.x + threadIdx.x;
    if (e < NE) {
        float w = ew[e];
        g_norm[e] = -(g_dis[row[e]] * w * g_dis[col[e]]);
        atomicAdd(&g_cnt[col[e]], 1);
        out_ew[e] = w;
    }
}

__global__ void k_scan() {
    __shared__ int sh[1024];
    const int CH = 20;
    int tid = threadIdx.x;
    int base = tid * CH;
    int s = 0;
    for (int i = 0; i < CH; i++) {
        int idx = base + i;
        if (idx < NN) s += g_cnt[idx];
    }
    sh[tid] = s;
    __syncthreads();
    for (int off = 1; off < 1024; off <<= 1) {
        int v = (tid >= off) ? sh[tid - off] : 0;
        __syncthreads();
        sh[tid] += v;
        __syncthreads();
    }
    int run = (tid == 0) ? 0 : sh[tid - 1];
    for (int i = 0; i < CH; i++) {
        int idx = base + i;
        if (idx < NN) { g_ptr[idx] = run; run += g_cnt[idx]; }
    }
    if (tid == 1023) g_ptr[NN] = sh[1023];
}

__global__ void k_scatter(const int* __restrict__ col) {
    int e = blockIdx.x * blockDim.x + threadIdx.x;
    if (e < NE) {
        int c = col[e];
        int pos = g_ptr[c] + atomicAdd(&g_cur[c], 1);
        g_eid[pos] = e;
    }
}

__global__ void k_sortfill(const int* __restrict__ row) {
    int c = blockIdx.x * blockDim.x + threadIdx.x;
    if (c >= NN) return;
    int b = g_ptr[c], t = g_ptr[c + 1];
    for (int i = b + 1; i < t; i++) {
        int v = g_eid[i];
        int j = i - 1;
        while (j >= b && g_eid[j] > v) { g_eid[j + 1] = g_eid[j]; j--; }
        g_eid[j + 1] = v;
    }
    for (int p = b; p < t; p++) {
        int e = g_eid[p];
        g_src[p] = row[e];
        g_w[p] = g_norm[e];
    }
}

// ==================== weight prep: transpose + bf16 hi/lo split ====================
// mode 0: B = cheb_w[l] [768,256] -> g_wch_{hi,lo}[l]; mode 1: B = w1 [1024,256] -> g_wcl_{hi,lo}
__global__ void k_prepB(const float* __restrict__ B, int K, int mode, int l) {
    int idx = blockIdx.x * blockDim.x + threadIdx.x;
    int Khalf = K >> 1;
    int total = 256 * Khalf;
    if (idx >= total) return;
    int n = idx & 255, kp = idx >> 8;
    float v0 = B[(size_t)(2 * kp) * 256 + n];
    float v1 = B[(size_t)(2 * kp + 1) * 256 + n];
    __nv_bfloat16 h0 = __float2bfloat16(v0), h1 = __float2bfloat16(v1);
    float r0 = v0 - __bfloat162float(h0), r1 = v1 - __bfloat162float(h1);
    __nv_bfloat16 l0 = __float2bfloat16(r0), l1 = __float2bfloat16(r1);
    size_t o = (size_t)n * Khalf + kp;
    if (mode == 0) {
        g_wch_hi[(size_t)l * 256 * (KCH / 2) + o] = packbf(h0, h1);
        g_wch_lo[(size_t)l * 256 * (KCH / 2) + o] = packbf(l0, l1);
    } else {
        g_wcl_hi[o] = packbf(h0, h1);
        g_wcl_lo[o] = packbf(l0, l1);
    }
}

// ==================== cheb propagation ====================
// T0 = features (layer 0) or g_h (later layers)
__global__ void k_copyT0(const float* __restrict__ feat, int use_feat) {
    int i = blockIdx.x * blockDim.x + threadIdx.x;
    if (i >= NN * DD) return;
    int n = i >> 8, d = i & 255;
    float v = use_feat ? feat[i] : g_h[i];
    g_tcat[(size_t)n * KCH + d] = v;
}

// phase 0: T1 = prop(T0); phase 1: T2 = 2*prop(T1) - T0.  All in g_tcat.
__global__ void k_prop(int phase) {
    int c = blockIdx.x * 2 + threadIdx.y;
    if (c >= NN) return;
    int t = threadIdx.x;  // 0..63, float4 each
    const float* xbase = g_tcat + (phase == 0 ? 0 : 256);

    float4 acc = make_float4(0.f, 0.f, 0.f, 0.f);
    int b = g_ptr[c], e = g_ptr[c + 1];
    int p = b;
    for (; p + 2 <= e; p += 2) {
        float w0 = g_w[p], w1 = g_w[p + 1];
        int s0 = g_src[p], s1 = g_src[p + 1];
        float4 v0 = *(const float4*)(xbase + (size_t)s0 * KCH + 4 * t);
        float4 v1 = *(const float4*)(xbase + (size_t)s1 * KCH + 4 * t);
        acc.x += w0 * v0.x + w1 * v1.x;
        acc.y += w0 * v0.y + w1 * v1.y;
        acc.z += w0 * v0.z + w1 * v1.z;
        acc.w += w0 * v0.w + w1 * v1.w;
    }
    if (p < e) {
        float w0 = g_w[p];
        int s0 = g_src[p];
        float4 v0 = *(const float4*)(xbase + (size_t)s0 * KCH + 4 * t);
        acc.x += w0 * v0.x; acc.y += w0 * v0.y;
        acc.z += w0 * v0.z; acc.w += w0 * v0.w;
    }
    if (phase == 0) {
        *(float4*)(g_tcat + (size_t)c * KCH + 256 + 4 * t) = acc;
    } else {
        float4 v0 = *(const float4*)(g_tcat + (size_t)c * KCH + 4 * t);
        acc.x = 2.f * acc.x - v0.x;
        acc.y = 2.f * acc.y - v0.y;
        acc.z = 2.f * acc.z - v0.z;
        acc.w = 2.f * acc.w - v0.w;
        *(float4*)(g_tcat + (size_t)c * KCH + 512 + 4 * t) = acc;
    }
}

// ==================== mma.sync bf16 GEMM ====================
// C[128-tile, 128-tile] = A[.,K] @ W[K,256], bf16 hi/lo 3-product split, fp32 accum in regs.
// Grid (2, 157). 8 warps = 2(M) x 4(N); warp tile 64x32; K-chunk 64.
// EPI 0: A=g_tcat (K=768), W=g_wch[l]; relu -> g_h, g_jk[:, l*256..]
// EPI 1: A=g_jk  (K=1024), W=g_wcl;  +bias, relu, BN -> g_z
#define SA_STRIDE 72        // bf16 elems per smem row (64 + 8 pad)
#define SA_BYTES (128 * SA_STRIDE * 2)   // 18432
#define GSM_TOTAL (4 * SA_BYTES)         // Ahi | Alo | Bhi | Blo = 73728

template <int EPI>
__global__ void __launch_bounds__(256)
k_mmagemm(int l, const float* __restrict__ bias, const float* __restrict__ gamma,
          const float* __restrict__ beta, const float* __restrict__ mean,
          const float* __restrict__ var) {
    extern __shared__ char smem[];
    const int K = (EPI == 0) ? KCH : KCL;
    const float* A = (EPI == 0) ? g_tcat : g_jk;
    const uint32_t* Bhi = (EPI == 0) ? (g_wch_hi + (size_t)l * 256 * (KCH / 2)) : g_wcl_hi;
    const uint32_t* Blo = (EPI == 0) ? (g_wch_lo + (size_t)l * 256 * (KCH / 2)) : g_wcl_lo;
    const int jkoff = l * 256;
    const int Khalf = K >> 1;

    char* AhiS = smem;
    char* AloS = smem + SA_BYTES;
    char* BhiS = smem + 2 * SA_BYTES;
    char* BloS = smem + 3 * SA_BYTES;
    uint32_t sAhi = smem_u32(AhiS), sAlo = smem_u32(AloS);
    uint32_t sBhi = smem_u32(BhiS), sBlo = smem_u32(BloS);

    int tid = threadIdx.x;
    int wid = tid >> 5, lane = tid & 31;
    int wm = wid >> 2, wn = wid & 3;          // warp tile: rows wm*64, cols wn*32
    int brow = blockIdx.y * 128;
    int bcol = blockIdx.x * 128;              // 0 or 128 (of 256 output cols)

    float acc[4][4][4];
#pragma unroll
    for (int i = 0; i < 4; i++)
#pragma unroll
        for (int j = 0; j < 4; j++)
#pragma unroll
            for (int q = 0; q < 4; q++) acc[i][j][q] = 0.f;

    // ldmatrix lane addressing (within warp tile)
    int a_mi = lane >> 3;                     // matrix index 0..3
    int a_row = ((a_mi & 1) << 3) + (lane & 7);
    int a_koff = (a_mi >> 1) << 3;
    int b_nrow = (((lane >> 4) & 1) << 3) + (lane & 7);
    int b_koff = ((lane >> 3) & 1) << 3;

    const int nchunks = K >> 6;
    for (int c = 0; c < nchunks; c++) {
        int k0 = c << 6;
        // --- stage A: [128 rows][64 k] fp32 -> bf16 hi/lo, stride 72 ---
#pragma unroll
        for (int i = 0; i < 16; i++) {
            int idx = tid + i * 256;          // 0..4095
            int r = idx >> 5, kp = idx & 31;  // row, k-pair
            int gr = brow + r;
            float2 v = (gr < NN) ? *(const float2*)(A + (size_t)gr * K + k0 + 2 * kp)
                                 : make_float2(0.f, 0.f);
            __nv_bfloat16 h0 = __float2bfloat16(v.x);
            __nv_bfloat16 h1 = __float2bfloat16(v.y);
            float r0 = v.x - __bfloat162float(h0);
            float r1 = v.y - __bfloat162float(h1);
            __nv_bfloat16 l0 = __float2bfloat16(r0), l1 = __float2bfloat16(r1);
            uint32_t off = (uint32_t)(r * (SA_STRIDE * 2) + kp * 4);
            *(uint32_t*)(AhiS + off) = packbf(h0, h1);
            *(uint32_t*)(AloS + off) = packbf(l0, l1);
        }
        // --- stage B: [128 n][64 k] preconverted bf16x2, n offset by bcol ---
#pragma unroll
        for (int i = 0; i < 16; i++) {
            int idx = tid + i * 256;
            int n = idx >> 5, kp = idx & 31;
            size_t gi = (size_t)(bcol + n) * Khalf + (k0 >> 1) + kp;
            uint32_t off = (uint32_t)(n * (SA_STRIDE * 2) + kp * 4);
            *(uint32_t*)(BhiS + off) = Bhi[gi];
            *(uint32_t*)(BloS + off) = Blo[gi];
        }
        __syncthreads();

#pragma unroll
        for (int kb = 0; kb < 4; kb++) {
            uint32_t ah[4][4], al[4][4], bh[2][4], bl[2][4];
#pragma unroll
            for (int mb = 0; mb < 4; mb++) {
                uint32_t off = (uint32_t)((wm * 64 + mb * 16 + a_row) * (SA_STRIDE * 2)
                                          + (kb * 16 + a_koff) * 2);
                ldm_x4(ah[mb], sAhi + off);
                ldm_x4(al[mb], sAlo + off);
            }
#pragma unroll
            for (int np = 0; np < 2; np++) {
                uint32_t off = (uint32_t)((wn * 32 + np * 16 + b_nrow) * (SA_STRIDE * 2)
                                          + (kb * 16 + b_koff) * 2);
                ldm_x4(bh[np], sBhi + off);
                ldm_x4(bl[np], sBlo + off);
            }
#pragma unroll
            for (int mb = 0; mb < 4; mb++)
#pragma unroll
                for (int nb = 0; nb < 4; nb++) {
                    int p = nb >> 1, q = (nb & 1) * 2;
                    mma16816(acc[mb][nb], ah[mb], bh[p][q], bh[p][q + 1]);
                    mma16816(acc[mb][nb], al[mb], bh[p][q], bh[p][q + 1]);
                    mma16816(acc[mb][nb], ah[mb], bl[p][q], bl[p][q + 1]);
                }
        }
        __syncthreads();
    }

    // ---- epilogue: fragment (m,n) mapping: c0,c1 -> (gr, cg..cg+1); c2,c3 -> (gr+8, ...) ----
    int gr_base = brow + wm * 64 + (lane >> 2);
    int cg_base = bcol + wn * 32 + (lane & 3) * 2;
#pragma unroll
    for (int mb = 0; mb < 4; mb++) {
#pragma unroll
        for (int nb = 0; nb < 4; nb++) {
            int cg = cg_base + nb * 8;       // global col 0..255
            int r0 = gr_base + mb * 16;
            int r1 = r0 + 8;
            float* a = acc[mb][nb];
            if (EPI == 0) {
                if (r0 < NN) {
                    float2 v = make_float2(fmaxf(a[0], 0.f), fmaxf(a[1], 0.f));
                    *(float2*)(g_h + (size_t)r0 * 256 + cg) = v;
                    *(float2*)(g_jk + (size_t)r0 * 1024 + jkoff + cg) = v;
                }
                if (r1 < NN) {
                    float2 v = make_float2(fmaxf(a[2], 0.f), fmaxf(a[3], 0.f));
                    *(float2*)(g_h + (size_t)r1 * 256 + cg) = v;
                    *(float2*)(g_jk + (size_t)r1 * 1024 + jkoff + cg) = v;
                }
            } else {
                float b0 = bias[cg], b1 = bias[cg + 1];
                float s0 = gamma[cg] * rsqrtf(var[cg] + BN_EPS);
                float s1 = gamma[cg + 1] * rsqrtf(var[cg + 1] + BN_EPS);
                float m0 = mean[cg], m1 = mean[cg + 1];
                float t0 = beta[cg], t1 = beta[cg + 1];
                if (r0 < NN) {
                    float2 v;
                    v.x = (fmaxf(a[0] + b0, 0.f) - m0) * s0 + t0;
                    v.y = (fmaxf(a[1] + b1, 0.f) - m1) * s1 + t1;
                    *(float2*)(g_z + (size_t)r0 * 256 + cg) = v;
                }
                if (r1 < NN) {
                    float2 v;
                    v.x = (fmaxf(a[2] + b0, 0.f) - m0) * s0 + t0;
                    v.y = (fmaxf(a[3] + b1, 0.f) - m1) * s1 + t1;
                    *(float2*)(g_z + (size_t)r1 * 256 + cg) = v;
                }
            }
        }
    }
}

// ==================== final projection [256] -> [2] ====================
__global__ void k_logit(const float* __restrict__ w2, const float* __restrict__ b2,
                        float* __restrict__ out) {
    int gw = (blockIdx.x * blockDim.x + threadIdx.x) >> 5;
    int lane = threadIdx.x & 31;
    if (gw >= NN) return;
    const float* z = g_z + (size_t)gw * 256;
    float a0 = 0.f, a1 = 0.f;
#pragma unroll
    for (int i = lane; i < 256; i += 32) {
        float zv = z[i];
        a0 += zv * w2[i * 2];
        a1 += zv * w2[i * 2 + 1];
    }
#pragma unroll
    for (int off = 16; off; off >>= 1) {
        a0 += __shfl_down_sync(0xffffffffu, a0, off);
        a1 += __shfl_down_sync(0xffffffffu, a1, off);
    }
    if (lane == 0) {
        out[gw * 2 + 0] = a0 + b2[0];
        out[gw * 2 + 1] = a1 + b2[1];
    }
}

// ==================== launch ====================
extern "C" void kernel_launch(void* const* d_in, const int* in_sizes, int n_in,
                              void* d_out, int out_size) {
    const float* features = (const float*)d_in[0];
    const int*   eidx     = (const int*)d_in[1];
    const float* ew       = (const float*)d_in[3];   // d_in[2] edgenet_input unused (eval)
    const float* cheb_w   = (const float*)d_in[4];
    const float* w1       = (const float*)d_in[5];
    const float* b1       = (const float*)d_in[6];
    const float* gamma    = (const float*)d_in[7];
    const float* beta     = (const float*)d_in[8];
    const float* mean     = (const float*)d_in[9];
    const float* var      = (const float*)d_in[10];
    const float* w2       = (const float*)d_in[11];
    const float* b2       = (const float*)d_in[12];

    const int* row = eidx;
    const int* col = eidx + NE;
    float* out_logit = (float*)d_out;
    float* out_ew    = (float*)d_out + NN * 2;

    cudaFuncSetAttribute(k_mmagemm<0>, cudaFuncAttributeMaxDynamicSharedMemorySize, GSM_TOTAL);
    cudaFuncSetAttribute(k_mmagemm<1>, cudaFuncAttributeMaxDynamicSharedMemorySize, GSM_TOTAL);

    // graph normalization + CSC build
    k_zero<<<(NN + 255) / 256, 256>>>();
    k_deg<<<(NE + 255) / 256, 256>>>(row, ew);
    k_dis<<<(NN + 255) / 256, 256>>>();
    k_norm<<<(NE + 255) / 256, 256>>>(row, col, ew, out_ew);
    k_scan<<<1, 1024>>>();
    k_scatter<<<(NE + 255) / 256, 256>>>(col);
    k_sortfill<<<(NN + 127) / 128, 128>>>(row);

    // weight prep: transpose + bf16 hi/lo split
    {
        int tch = 256 * (KCH / 2);
        for (int l = 0; l < LGC; l++)
            k_prepB<<<(tch + 255) / 256, 256>>>(cheb_w + (size_t)l * 3 * 256 * 256, KCH, 0, l);
        int tcl = 256 * (KCL / 2);
        k_prepB<<<(tcl + 255) / 256, 256>>>(w1, KCL, 1, 0);
    }

    dim3 ggrid(2, (NN + 127) / 128);  // (2, 157)
    for (int l = 0; l < LGC; l++) {
        int use_feat = (l == 0) ? 1 : 0;
        k_copyT0<<<(NN * DD + 255) / 256, 256>>>(features, use_feat);
        k_prop<<<(NN + 1) / 2, dim3(64, 2)>>>(0);
        k_prop<<<(NN + 1) / 2, dim3(64, 2)>>>(1);
        k_mmagemm<0><<<ggrid, 256, GSM_TOTAL>>>(l, nullptr, nullptr, nullptr, nullptr, nullptr);
    }
    k_mmagemm<1><<<ggrid, 256, GSM_TOTAL>>>(0, b1, gamma, beta, mean, var);
    k_logit<<<(NN * 32 + 255) / 256, 256>>>(w2, b2, out_logit);
}

// round 9
// speedup vs baseline: 1.7671x; 1.0337x over previous
#include <cuda_runtime.h>
#include <cuda_bf16.h>
#include <cstdint>

#define NN 20000
#define NE 320000
#define DD 256
#define LGC 4
#define KCH 768
#define KCL 1024
#define BN_EPS 1e-5f

// ==================== scratch ====================
__device__ float g_deg[NN];
__device__ float g_dis[NN];
__device__ float g_norm[NE];
__device__ int   g_cnt[NN];
__device__ int   g_cur[NN];
__device__ int   g_ptr[NN + 1];
__device__ int   g_eid[NE];
__device__ int   g_src[NE];
__device__ float g_w[NE];
__device__ float g_t1[(size_t)NN * DD];      // T1 = prop(T0)
__device__ float g_t2[(size_t)NN * DD];      // T2 = 2*prop(T1) - T0
__device__ float g_jk[(size_t)NN * 1024];    // JK concat [N, 1024]; slice l is layer-l output
// transposed bf16 hi/lo weights: [256 n][K/2 kpairs] as uint32 (bf16x2, low half = even k)
__device__ uint32_t g_wch_hi[LGC * 256 * (KCH / 2)];
__device__ uint32_t g_wch_lo[LGC * 256 * (KCH / 2)];
__device__ uint32_t g_wcl_hi[256 * (KCL / 2)];
__device__ uint32_t g_wcl_lo[256 * (KCL / 2)];

__device__ __forceinline__ uint32_t packbf(__nv_bfloat16 a, __nv_bfloat16 b) {
    return (uint32_t)__bfloat16_as_ushort(a) | ((uint32_t)__bfloat16_as_ushort(b) << 16);
}

__device__ __forceinline__ uint32_t smem_u32(const void* p) {
    uint32_t a;
    asm("{ .reg .u64 t; cvta.to.shared.u64 t, %1; cvt.u32.u64 %0, t; }" : "=r"(a) : "l"(p));
    return a;
}

__device__ __forceinline__ void ldm_x4(uint32_t r[4], uint32_t addr) {
    asm volatile("ldmatrix.sync.aligned.m8n8.x4.shared.b16 {%0,%1,%2,%3}, [%4];"
                 : "=r"(r[0]), "=r"(r[1]), "=r"(r[2]), "=r"(r[3]) : "r"(addr));
}

__device__ __forceinline__ void mma16816(float c[4], const uint32_t a[4], const uint32_t b0,
                                         const uint32_t b1) {
    asm volatile(
        "mma.sync.aligned.m16n8k16.row.col.f32.bf16.bf16.f32 "
        "{%0,%1,%2,%3}, {%4,%5,%6,%7}, {%8,%9}, {%0,%1,%2,%3};"
        : "+f"(c[0]), "+f"(c[1]), "+f"(c[2]), "+f"(c[3])
        : "r"(a[0]), "r"(a[1]), "r"(a[2]), "r"(a[3]), "r"(b0), "r"(b1));
}

// ==================== setup kernels ====================
__global__ void k_zero() {
    int i = blockIdx.x * blockDim.x + threadIdx.x;
    if (i < NN) { g_deg[i] = 0.f; g_cnt[i] = 0; g_cur[i] = 0; }
}

__global__ void k_deg(const int* __restrict__ row, const float* __restrict__ ew) {
    int e = blockIdx.x * blockDim.x + threadIdx.x;
    if (e < NE) atomicAdd(&g_deg[row[e]], ew[e]);
}

__global__ void k_dis() {
    int i = blockIdx.x * blockDim.x + threadIdx.x;
    if (i < NN) {
        float d = g_deg[i];
        float y = 0.f;
        if (d > 0.f) {
            y = rsqrtf(d);
            y = y * (1.5f - 0.5f * d * y * y);  // Newton refine
        }
        g_dis[i] = y;
    }
}

__global__ void k_norm(const int* __restrict__ row, const int* __restrict__ col,
                       const float* __restrict__ ew, float* __restrict__ out_ew) {
    int e = blockIdx.x * blockDim.x + threadIdx.x;
    if (e < NE) {
        float w = ew[e];
        g_norm[e] = -(g_dis[row[e]] * w * g_dis[col[e]]);
        atomicAdd(&g_cnt[col[e]], 1);
        out_ew[e] = w;
    }
}

__global__ void k_scan() {
    __shared__ int sh[1024];
    const int CH = 20;
    int tid = threadIdx.x;
    int base = tid * CH;
    int s = 0;
    for (int i = 0; i < CH; i++) {
        int idx = base + i;
        if (idx < NN) s += g_cnt[idx];
    }
    sh[tid] = s;
    __syncthreads();
    for (int off = 1; off < 1024; off <<= 1) {
        int v = (tid >= off) ? sh[tid - off] : 0;
        __syncthreads();
        sh[tid] += v;
        __syncthreads();
    }
    int run = (tid == 0) ? 0 : sh[tid - 1];
    for (int i = 0; i < CH; i++) {
        int idx = base + i;
        if (idx < NN) { g_ptr[idx] = run; run += g_cnt[idx]; }
    }
    if (tid == 1023) g_ptr[NN] = sh[1023];
}

__global__ void k_scatter(const int* __restrict__ col) {
    int e = blockIdx.x * blockDim.x + threadIdx.x;
    if (e < NE) {
        int c = col[e];
        int pos = g_ptr[c] + atomicAdd(&g_cur[c], 1);
        g_eid[pos] = e;
    }
}

__global__ void k_sortfill(const int* __restrict__ row) {
    int c = blockIdx.x * blockDim.x + threadIdx.x;
    if (c >= NN) return;
    int b = g_ptr[c], t = g_ptr[c + 1];
    for (int i = b + 1; i < t; i++) {
        int v = g_eid[i];
        int j = i - 1;
        while (j >= b && g_eid[j] > v) { g_eid[j + 1] = g_eid[j]; j--; }
        g_eid[j + 1] = v;
    }
    for (int p = b; p < t; p++) {
        int e = g_eid[p];
        g_src[p] = row[e];
        g_w[p] = g_norm[e];
    }
}

// ==================== weight prep: transpose + bf16 hi/lo split ====================
__global__ void k_prepB(const float* __restrict__ B, int K, int mode, int l) {
    int idx = blockIdx.x * blockDim.x + threadIdx.x;
    int Khalf = K >> 1;
    int total = 256 * Khalf;
    if (idx >= total) return;
    int n = idx & 255, kp = idx >> 8;
    float v0 = B[(size_t)(2 * kp) * 256 + n];
    float v1 = B[(size_t)(2 * kp + 1) * 256 + n];
    __nv_bfloat16 h0 = __float2bfloat16(v0), h1 = __float2bfloat16(v1);
    float r0 = v0 - __bfloat162float(h0), r1 = v1 - __bfloat162float(h1);
    __nv_bfloat16 l0 = __float2bfloat16(r0), l1 = __float2bfloat16(r1);
    size_t o = (size_t)n * Khalf + kp;
    if (mode == 0) {
        g_wch_hi[(size_t)l * 256 * (KCH / 2) + o] = packbf(h0, h1);
        g_wch_lo[(size_t)l * 256 * (KCH / 2) + o] = packbf(l0, l1);
    } else {
        g_wcl_hi[o] = packbf(h0, h1);
        g_wcl_lo[o] = packbf(l0, l1);
    }
}

// ==================== cheb propagation ====================
// T0 source: l==0 -> features (stride 256); l>0 -> g_jk + (l-1)*256 (stride 1024).
// phase 0: g_t1 = prop(T0);  phase 1: g_t2 = 2*prop(g_t1) - T0.
__global__ void k_prop(const float* __restrict__ feat, int l, int phase) {
    int c = blockIdx.x * 2 + threadIdx.y;
    if (c >= NN) return;
    int t = threadIdx.x;  // 0..63, float4 each
    const float* xin = (l == 0) ? feat : (g_jk + (size_t)(l - 1) * 256);
    int xstride = (l == 0) ? 256 : 1024;
    const float* xb;
    int xs;
    if (phase == 0) { xb = xin; xs = xstride; }
    else            { xb = g_t1; xs = 256; }

    float4 acc = make_float4(0.f, 0.f, 0.f, 0.f);
    int b = g_ptr[c], e = g_ptr[c + 1];
    int p = b;
    for (; p + 4 <= e; p += 4) {
        float w0 = g_w[p], w1 = g_w[p + 1], w2 = g_w[p + 2], w3 = g_w[p + 3];
        int s0 = g_src[p], s1 = g_src[p + 1], s2 = g_src[p + 2], s3 = g_src[p + 3];
        float4 v0 = *(const float4*)(xb + (size_t)s0 * xs + 4 * t);
        float4 v1 = *(const float4*)(xb + (size_t)s1 * xs + 4 * t);
        float4 v2 = *(const float4*)(xb + (size_t)s2 * xs + 4 * t);
        float4 v3 = *(const float4*)(xb + (size_t)s3 * xs + 4 * t);
        acc.x += w0 * v0.x + w1 * v1.x + w2 * v2.x + w3 * v3.x;
        acc.y += w0 * v0.y + w1 * v1.y + w2 * v2.y + w3 * v3.y;
        acc.z += w0 * v0.z + w1 * v1.z + w2 * v2.z + w3 * v3.z;
        acc.w += w0 * v0.w + w1 * v1.w + w2 * v2.w + w3 * v3.w;
    }
    for (; p < e; p++) {
        float w0 = g_w[p];
        int s0 = g_src[p];
        float4 v0 = *(const float4*)(xb + (size_t)s0 * xs + 4 * t);
        acc.x += w0 * v0.x; acc.y += w0 * v0.y;
        acc.z += w0 * v0.z; acc.w += w0 * v0.w;
    }
    if (phase == 0) {
        *(float4*)(g_t1 + (size_t)c * 256 + 4 * t) = acc;
    } else {
        float4 v0 = *(const float4*)(xin + (size_t)c * xstride + 4 * t);
        acc.x = 2.f * acc.x - v0.x;
        acc.y = 2.f * acc.y - v0.y;
        acc.z = 2.f * acc.z - v0.z;
        acc.w = 2.f * acc.w - v0.w;
        *(float4*)(g_t2 + (size_t)c * 256 + 4 * t) = acc;
    }
}

// ==================== mma.sync bf16 GEMM (full-N CTA) ====================
// Grid (157), 512 threads = 16 warps (2 M x 8 N); warp tile 64x32; K-chunk 64.
// EPI 0: A = [T0|T1|T2] segmented (T0 from features/g_jk, T1=g_t1, T2=g_t2), K=768,
//        W = g_wch[l]; relu -> g_jk[:, l*256..]
// EPI 1: A = g_jk (K=1024), W = g_wcl; +bias, relu, BN, fused [256]->[2] logit -> out
#define SA_STRIDE 72
#define SA_ROWB (SA_STRIDE * 2)              // 144
#define SA_BYTES (128 * SA_ROWB)             // 18432
#define SB_BYTES (256 * SA_ROWB)             // 36864
#define GSM_TOTAL (2 * SA_BYTES + 2 * SB_BYTES)  // 110592

template <int EPI>
__global__ void __launch_bounds__(512)
k_mmagemm(int l, const float* __restrict__ feat,
          const float* __restrict__ bias, const float* __restrict__ gamma,
          const float* __restrict__ beta, const float* __restrict__ mean,
          const float* __restrict__ var, const float* __restrict__ w2,
          const float* __restrict__ b2, float* __restrict__ out) {
    extern __shared__ char smem[];
    __shared__ float lpart[128][8][2];
    const int K = (EPI == 0) ? KCH : KCL;
    const uint32_t* Bhi = (EPI == 0) ? (g_wch_hi + (size_t)l * 256 * (KCH / 2)) : g_wcl_hi;
    const uint32_t* Blo = (EPI == 0) ? (g_wch_lo + (size_t)l * 256 * (KCH / 2)) : g_wcl_lo;
    const int jkoff = l * 256;
    const int Khalf = K >> 1;
    const float* xin = (l == 0) ? feat : (g_jk + (size_t)(l - 1) * 256);
    const int xstride = (l == 0) ? 256 : 1024;

    char* AhiS = smem;
    char* AloS = smem + SA_BYTES;
    char* BhiS = smem + 2 * SA_BYTES;
    char* BloS = smem + 2 * SA_BYTES + SB_BYTES;
    uint32_t sAhi = smem_u32(AhiS), sAlo = smem_u32(AloS);
    uint32_t sBhi = smem_u32(BhiS), sBlo = smem_u32(BloS);

    int tid = threadIdx.x;
    int wid = tid >> 5, lane = tid & 31;
    int wm = wid >> 3, wn = wid & 7;
    int brow = blockIdx.x * 128;

    float acc[4][4][4];
#pragma unroll
    for (int i = 0; i < 4; i++)
#pragma unroll
        for (int j = 0; j < 4; j++)
#pragma unroll
            for (int q = 0; q < 4; q++) acc[i][j][q] = 0.f;

    int a_mi = lane >> 3;
    int a_row = ((a_mi & 1) << 3) + (lane & 7);
    int a_koff = (a_mi >> 1) << 3;
    int b_nrow = (((lane >> 4) & 1) << 3) + (lane & 7);
    int b_koff = ((lane >> 3) & 1) << 3;

    const int nchunks = K >> 6;
    for (int c = 0; c < nchunks; c++) {
        int k0 = c << 6;
        const float* Abase;
        int Astride;
        if (EPI == 0) {
            int seg = k0 >> 8, koff = k0 & 255;
            if (seg == 0)      { Abase = xin + koff;  Astride = xstride; }
            else if (seg == 1) { Abase = g_t1 + koff; Astride = 256; }
            else               { Abase = g_t2 + koff; Astride = 256; }
        } else {
            Abase = g_jk + k0;
            Astride = 1024;
        }
#pragma unroll
        for (int i = 0; i < 8; i++) {
            int idx = tid + i * 512;
            int r = idx >> 5, kp = idx & 31;
            int gr = brow + r;
            float2 v = (gr < NN) ? *(const float2*)(Abase + (size_t)gr * Astride + 2 * kp)
                                 : make_float2(0.f, 0.f);
            __nv_bfloat16 h0 = __float2bfloat16(v.x);
            __nv_bfloat16 h1 = __float2bfloat16(v.y);
            float r0 = v.x - __bfloat162float(h0);
            float r1 = v.y - __bfloat162float(h1);
            __nv_bfloat16 l0 = __float2bfloat16(r0), l1 = __float2bfloat16(r1);
            uint32_t off = (uint32_t)(r * SA_ROWB + kp * 4);
            *(uint32_t*)(AhiS + off) = packbf(h0, h1);
            *(uint32_t*)(AloS + off) = packbf(l0, l1);
        }
#pragma unroll
        for (int i = 0; i < 16; i++) {
            int idx = tid + i * 512;
            int n = idx >> 5, kp = idx & 31;
            size_t gi = (size_t)n * Khalf + (k0 >> 1) + kp;
            uint32_t off = (uint32_t)(n * SA_ROWB + kp * 4);
            *(uint32_t*)(BhiS + off) = Bhi[gi];
            *(uint32_t*)(BloS + off) = Blo[gi];
        }
        __syncthreads();

#pragma unroll
        for (int kb = 0; kb < 4; kb++) {
            uint32_t ah[4][4], al[4][4], bh[2][4], bl[2][4];
#pragma unroll
            for (int mb = 0; mb < 4; mb++) {
                uint32_t off = (uint32_t)((wm * 64 + mb * 16 + a_row) * SA_ROWB
                                          + (kb * 16 + a_koff) * 2);
                ldm_x4(ah[mb], sAhi + off);
                ldm_x4(al[mb], sAlo + off);
            }
#pragma unroll
            for (int np = 0; np < 2; np++) {
                uint32_t off = (uint32_t)((wn * 32 + np * 16 + b_nrow) * SA_ROWB
                                          + (kb * 16 + b_koff) * 2);
                ldm_x4(bh[np], sBhi + off);
                ldm_x4(bl[np], sBlo + off);
            }
#pragma unroll
            for (int mb = 0; mb < 4; mb++)
#pragma unroll
                for (int nb = 0; nb < 4; nb++) {
                    int p = nb >> 1, q = (nb & 1) * 2;
                    mma16816(acc[mb][nb], ah[mb], bh[p][q], bh[p][q + 1]);
                    mma16816(acc[mb][nb], al[mb], bh[p][q], bh[p][q + 1]);
                    mma16816(acc[mb][nb], ah[mb], bl[p][q], bl[p][q + 1]);
                }
        }
        __syncthreads();
    }

    int gr_base = brow + wm * 64 + (lane >> 2);
    int cg_base = wn * 32 + (lane & 3) * 2;
    if (EPI == 0) {
#pragma unroll
        for (int mb = 0; mb < 4; mb++) {
#pragma unroll
            for (int nb = 0; nb < 4; nb++) {
                int cg = cg_base + nb * 8;
                int r0 = gr_base + mb * 16;
                int r1 = r0 + 8;
                float* a = acc[mb][nb];
                if (r0 < NN) {
                    float2 v = make_float2(fmaxf(a[0], 0.f), fmaxf(a[1], 0.f));
                    *(float2*)(g_jk + (size_t)r0 * 1024 + jkoff + cg) = v;
                }
                if (r1 < NN) {
                    float2 v = make_float2(fmaxf(a[2], 0.f), fmaxf(a[3], 0.f));
                    *(float2*)(g_jk + (size_t)r1 * 1024 + jkoff + cg) = v;
                }
            }
        }
    } else {
#pragma unroll
        for (int mb = 0; mb < 4; mb++) {
            float p0a = 0.f, p0b = 0.f, p1a = 0.f, p1b = 0.f;
#pragma unroll
            for (int nb = 0; nb < 4; nb++) {
                int cg = cg_base + nb * 8;
                float* a = acc[mb][nb];
                float b0 = bias[cg], b1 = bias[cg + 1];
                float s0 = gamma[cg] * rsqrtf(var[cg] + BN_EPS);
                float s1 = gamma[cg + 1] * rsqrtf(var[cg + 1] + BN_EPS);
                float m0 = mean[cg], m1 = mean[cg + 1];
                float t0 = beta[cg], t1 = beta[cg + 1];
                float w00 = w2[cg * 2], w01 = w2[cg * 2 + 1];
                float w10 = w2[(cg + 1) * 2], w11 = w2[(cg + 1) * 2 + 1];
                float z0x = (fmaxf(a[0] + b0, 0.f) - m0) * s0 + t0;
                float z0y = (fmaxf(a[1] + b1, 0.f) - m1) * s1 + t1;
                float z1x = (fmaxf(a[2] + b0, 0.f) - m0) * s0 + t0;
                float z1y = (fmaxf(a[3] + b1, 0.f) - m1) * s1 + t1;
                p0a += z0x * w00 + z0y * w10;
                p0b += z0x * w01 + z0y * w11;
                p1a += z1x * w00 + z1y * w10;
                p1b += z1x * w01 + z1y * w11;
            }
#pragma unroll
            for (int m = 1; m <= 2; m <<= 1) {
                p0a += __shfl_xor_sync(0xffffffffu, p0a, m);
                p0b += __shfl_xor_sync(0xffffffffu, p0b, m);
                p1a += __shfl_xor_sync(0xffffffffu, p1a, m);
                p1b += __shfl_xor_sync(0xffffffffu, p1b, m);
            }
            if ((lane & 3) == 0) {
                int rl0 = wm * 64 + mb * 16 + (lane >> 2);
                lpart[rl0][wn][0] = p0a;
                lpart[rl0][wn][1] = p0b;
                lpart[rl0 + 8][wn][0] = p1a;
                lpart[rl0 + 8][wn][1] = p1b;
            }
        }
        __syncthreads();
        if (tid < 128) {
            int gr = brow + tid;
            if (gr < NN) {
                float s0 = 0.f, s1 = 0.f;
#pragma unroll
                for (int w = 0; w < 8; w++) {
                    s0 += lpart[tid][w][0];
                    s1 += lpart[tid][w][1];
                }
                out[gr * 2 + 0] = s0 + b2[0];
                out[gr * 2 + 1] = s1 + b2[1];
            }
        }
    }
}

// ==================== launch ====================
extern "C" void kernel_launch(void* const* d_in, const int* in_sizes, int n_in,
                              void* d_out, int out_size) {
    const float* features = (const float*)d_in[0];
    const int*   eidx     = (const int*)d_in[1];
    const float* ew       = (const float*)d_in[3];   // d_in[2] edgenet_input unused (eval)
    const float* cheb_w   = (const float*)d_in[4];
    const float* w1       = (const float*)d_in[5];
    const float* b1       = (const float*)d_in[6];
    const float* gamma    = (const float*)d_in[7];
    const float* beta     = (const float*)d_in[8];
    const float* mean     = (const float*)d_in[9];
    const float* var      = (const float*)d_in[10];
    const float* w2       = (const float*)d_in[11];
    const float* b2       = (const float*)d_in[12];

    const int* row = eidx;
    const int* col = eidx + NE;
    float* out_logit = (float*)d_out;
    float* out_ew    = (float*)d_out + NN * 2;

    cudaFuncSetAttribute(k_mmagemm<0>, cudaFuncAttributeMaxDynamicSharedMemorySize, GSM_TOTAL);
    cudaFuncSetAttribute(k_mmagemm<1>, cudaFuncAttributeMaxDynamicSharedMemorySize, GSM_TOTAL);

    // graph normalization + CSC build
    k_zero<<<(NN + 255) / 256, 256>>>();
    k_deg<<<(NE + 255) / 256, 256>>>(row, ew);
    k_dis<<<(NN + 255) / 256, 256>>>();
    k_norm<<<(NE + 255) / 256, 256>>>(row, col, ew, out_ew);
    k_scan<<<1, 1024>>>();
    k_scatter<<<(NE + 255) / 256, 256>>>(col);
    k_sortfill<<<(NN + 127) / 128, 128>>>(row);

    // weight prep: transpose + bf16 hi/lo split
    {
        int tch = 256 * (KCH / 2);
        for (int l = 0; l < LGC; l++)
            k_prepB<<<(tch + 255) / 256, 256>>>(cheb_w + (size_t)l * 3 * 256 * 256, KCH, 0, l);
        int tcl = 256 * (KCL / 2);
        k_prepB<<<(tcl + 255) / 256, 256>>>(w1, KCL, 1, 0);
    }

    int ggrid = (NN + 127) / 128;  // 157
    for (int l = 0; l < LGC; l++) {
        k_prop<<<(NN + 1) / 2, dim3(64, 2)>>>(features, l, 0);
        k_prop<<<(NN + 1) / 2, dim3(64, 2)>>>(features, l, 1);
        k_mmagemm<0><<<ggrid, 512, GSM_TOTAL>>>(l, features, nullptr, nullptr, nullptr,
                                                nullptr, nullptr, nullptr, nullptr, nullptr);
    }
    k_mmagemm<1><<<ggrid, 512, GSM_TOTAL>>>(3, nullptr, b1, gamma, beta, mean, var,
                                            w2, b2, out_logit);
}

// round 10
// speedup vs baseline: 2.0142x; 1.1398x over previous
#include <cuda_runtime.h>
#include <cuda_bf16.h>
#include <cstdint>

#define NN 20000
#define NE 320000
#define DD 256
#define LGC 4
#define KCH 768
#define KCL 1024
#define BN_EPS 1e-5f

// ==================== scratch ====================
__device__ float g_deg[NN];
__device__ float g_dis[NN];
__device__ float g_norm[NE];
__device__ int   g_cnt[NN];
__device__ int   g_cur[NN];
__device__ int   g_ptr[NN + 1];
__device__ int   g_eid[NE];
__device__ int   g_src[NE];
__device__ float g_w[NE];
__device__ float g_t1[(size_t)NN * DD];        // T1 fp32 (prop phase-1 gather input)
__device__ float g_jk[(size_t)NN * 1024];      // JK fp32 (next-layer T0 gather input)
// packed bf16 hi/lo operand copies: word w = bf16x2 of cols (2w, 2w+1)
__device__ uint32_t g_fph[(size_t)NN * 128];   // features
__device__ uint32_t g_fpl[(size_t)NN * 128];
__device__ uint32_t g_t1ph[(size_t)NN * 128];  // T1
__device__ uint32_t g_t1pl[(size_t)NN * 128];
__device__ uint32_t g_t2ph[(size_t)NN * 128];  // T2 (no fp32 copy needed)
__device__ uint32_t g_t2pl[(size_t)NN * 128];
__device__ uint32_t g_jkph[(size_t)NN * 512];  // JK (classifier + next-layer T0 GEMM operand)
__device__ uint32_t g_jkpl[(size_t)NN * 512];
// transposed bf16 hi/lo weights: [256 n][K/2 kpairs]
__device__ uint32_t g_wch_hi[LGC * 256 * (KCH / 2)];
__device__ uint32_t g_wch_lo[LGC * 256 * (KCH / 2)];
__device__ uint32_t g_wcl_hi[256 * (KCL / 2)];
__device__ uint32_t g_wcl_lo[256 * (KCL / 2)];

__device__ __forceinline__ uint32_t packbf(__nv_bfloat16 a, __nv_bfloat16 b) {
    return (uint32_t)__bfloat16_as_ushort(a) | ((uint32_t)__bfloat16_as_ushort(b) << 16);
}

// split two fp32 into hi/lo bf16x2 words
__device__ __forceinline__ void split2(float x, float y, uint32_t& hi, uint32_t& lo) {
    __nv_bfloat16 h0 = __float2bfloat16(x), h1 = __float2bfloat16(y);
    float r0 = x - __bfloat162float(h0), r1 = y - __bfloat162float(h1);
    hi = packbf(h0, h1);
    lo = packbf(__float2bfloat16(r0), __float2bfloat16(r1));
}

__device__ __forceinline__ uint32_t smem_u32(const void* p) {
    uint32_t a;
    asm("{ .reg .u64 t; cvta.to.shared.u64 t, %1; cvt.u32.u64 %0, t; }" : "=r"(a) : "l"(p));
    return a;
}

__device__ __forceinline__ void ldm_x4(uint32_t r[4], uint32_t addr) {
    asm volatile("ldmatrix.sync.aligned.m8n8.x4.shared.b16 {%0,%1,%2,%3}, [%4];"
                 : "=r"(r[0]), "=r"(r[1]), "=r"(r[2]), "=r"(r[3]) : "r"(addr));
}

__device__ __forceinline__ void mma16816(float c[4], const uint32_t a[4], const uint32_t b0,
                                         const uint32_t b1) {
    asm volatile(
        "mma.sync.aligned.m16n8k16.row.col.f32.bf16.bf16.f32 "
        "{%0,%1,%2,%3}, {%4,%5,%6,%7}, {%8,%9}, {%0,%1,%2,%3};"
        : "+f"(c[0]), "+f"(c[1]), "+f"(c[2]), "+f"(c[3])
        : "r"(a[0]), "r"(a[1]), "r"(a[2]), "r"(a[3]), "r"(b0), "r"(b1));
}

__device__ __forceinline__ void cpa16(uint32_t dst, const void* src, int sz) {
    asm volatile("cp.async.cg.shared.global [%0], [%1], 16, %2;"
                 :: "r"(dst), "l"(src), "r"(sz));
}
#define CP_COMMIT() asm volatile("cp.async.commit_group;" ::: "memory")
#define CP_WAIT1()  asm volatile("cp.async.wait_group 1;" ::: "memory")
#define CP_WAIT0()  asm volatile("cp.async.wait_group 0;" ::: "memory")

// ==================== setup kernels ====================
__global__ void k_zero() {
    int i = blockIdx.x * blockDim.x + threadIdx.x;
    if (i < NN) { g_deg[i] = 0.f; g_cnt[i] = 0; g_cur[i] = 0; }
}

__global__ void k_deg(const int* __restrict__ row, const float* __restrict__ ew) {
    int e = blockIdx.x * blockDim.x + threadIdx.x;
    if (e < NE) atomicAdd(&g_deg[row[e]], ew[e]);
}

__global__ void k_dis() {
    int i = blockIdx.x * blockDim.x + threadIdx.x;
    if (i < NN) {
        float d = g_deg[i];
        float y = 0.f;
        if (d > 0.f) {
            y = rsqrtf(d);
            y = y * (1.5f - 0.5f * d * y * y);  // Newton refine
        }
        g_dis[i] = y;
    }
}

__global__ void k_norm(const int* __restrict__ row, const int* __restrict__ col,
                       const float* __restrict__ ew, float* __restrict__ out_ew) {
    int e = blockIdx.x * blockDim.x + threadIdx.x;
    if (e < NE) {
        float w = ew[e];
        g_norm[e] = -(g_dis[row[e]] * w * g_dis[col[e]]);
        atomicAdd(&g_cnt[col[e]], 1);
        out_ew[e] = w;
    }
}

__global__ void k_scan() {
    __shared__ int sh[1024];
    const int CH = 20;
    int tid = threadIdx.x;
    int base = tid * CH;
    int s = 0;
    for (int i = 0; i < CH; i++) {
        int idx = base + i;
        if (idx < NN) s += g_cnt[idx];
    }
    sh[tid] = s;
    __syncthreads();
    for (int off = 1; off < 1024; off <<= 1) {
        int v = (tid >= off) ? sh[tid - off] : 0;
        __syncthreads();
        sh[tid] += v;
        __syncthreads();
    }
    int run = (tid == 0) ? 0 : sh[tid - 1];
    for (int i = 0; i < CH; i++) {
        int idx = base + i;
        if (idx < NN) { g_ptr[idx] = run; run += g_cnt[idx]; }
    }
    if (tid == 1023) g_ptr[NN] = sh[1023];
}

__global__ void k_scatter(const int* __restrict__ col) {
    int e = blockIdx.x * blockDim.x + threadIdx.x;
    if (e < NE) {
        int c = col[e];
        int pos = g_ptr[c] + atomicAdd(&g_cur[c], 1);
        g_eid[pos] = e;
    }
}

__global__ void k_sortfill(const int* __restrict__ row) {
    int c = blockIdx.x * blockDim.x + threadIdx.x;
    if (c >= NN) return;
    int b = g_ptr[c], t = g_ptr[c + 1];
    for (int i = b + 1; i < t; i++) {
        int v = g_eid[i];
        int j = i - 1;
        while (j >= b && g_eid[j] > v) { g_eid[j + 1] = g_eid[j]; j--; }
        g_eid[j + 1] = v;
    }
    for (int p = b; p < t; p++) {
        int e = g_eid[p];
        g_src[p] = row[e];
        g_w[p] = g_norm[e];
    }
}

// ==================== operand prep ====================
// weights: transpose + bf16 hi/lo split
__global__ void k_prepB(const float* __restrict__ B, int K, int mode, int l) {
    int idx = blockIdx.x * blockDim.x + threadIdx.x;
    int Khalf = K >> 1;
    int total = 256 * Khalf;
    if (idx >= total) return;
    int n = idx & 255, kp = idx >> 8;
    uint32_t hi, lo;
    split2(B[(size_t)(2 * kp) * 256 + n], B[(size_t)(2 * kp + 1) * 256 + n], hi, lo);
    size_t o = (size_t)n * Khalf + kp;
    if (mode == 0) {
        g_wch_hi[(size_t)l * 256 * (KCH / 2) + o] = hi;
        g_wch_lo[(size_t)l * 256 * (KCH / 2) + o] = lo;
    } else {
        g_wcl_hi[o] = hi;
        g_wcl_lo[o] = lo;
    }
}

// features -> packed hi/lo
__global__ void k_prepA(const float* __restrict__ feat) {
    int idx = blockIdx.x * blockDim.x + threadIdx.x;
    if (idx >= NN * 128) return;
    int n = idx >> 7, w = idx & 127;
    float2 v = *(const float2*)(feat + (size_t)n * 256 + 2 * w);
    uint32_t hi, lo;
    split2(v.x, v.y, hi, lo);
    g_fph[idx] = hi;
    g_fpl[idx] = lo;
}

// ==================== cheb propagation ====================
// T0 source: l==0 -> features (stride 256); l>0 -> g_jk + (l-1)*256 (stride 1024).
// phase 0: T1 = prop(T0) -> g_t1 fp32 + g_t1p packed
// phase 1: T2 = 2*prop(T1) - T0 -> g_t2p packed only
__global__ void k_prop(const float* __restrict__ feat, int l, int phase) {
    int c = blockIdx.x * 2 + threadIdx.y;
    if (c >= NN) return;
    int t = threadIdx.x;  // 0..63, float4 each
    const float* xin = (l == 0) ? feat : (g_jk + (size_t)(l - 1) * 256);
    int xstride = (l == 0) ? 256 : 1024;
    const float* xb;
    int xs;
    if (phase == 0) { xb = xin; xs = xstride; }
    else            { xb = g_t1; xs = 256; }

    float4 acc = make_float4(0.f, 0.f, 0.f, 0.f);
    int b = g_ptr[c], e = g_ptr[c + 1];
    int p = b;
    for (; p + 4 <= e; p += 4) {
        float w0 = g_w[p], w1 = g_w[p + 1], w2 = g_w[p + 2], w3 = g_w[p + 3];
        int s0 = g_src[p], s1 = g_src[p + 1], s2 = g_src[p + 2], s3 = g_src[p + 3];
        float4 v0 = *(const float4*)(xb + (size_t)s0 * xs + 4 * t);
        float4 v1 = *(const float4*)(xb + (size_t)s1 * xs + 4 * t);
        float4 v2 = *(const float4*)(xb + (size_t)s2 * xs + 4 * t);
        float4 v3 = *(const float4*)(xb + (size_t)s3 * xs + 4 * t);
        acc.x += w0 * v0.x + w1 * v1.x + w2 * v2.x + w3 * v3.x;
        acc.y += w0 * v0.y + w1 * v1.y + w2 * v2.y + w3 * v3.y;
        acc.z += w0 * v0.z + w1 * v1.z + w2 * v2.z + w3 * v3.z;
        acc.w += w0 * v0.w + w1 * v1.w + w2 * v2.w + w3 * v3.w;
    }
    for (; p < e; p++) {
        float w0 = g_w[p];
        int s0 = g_src[p];
        float4 v0 = *(const float4*)(xb + (size_t)s0 * xs + 4 * t);
        acc.x += w0 * v0.x; acc.y += w0 * v0.y;
        acc.z += w0 * v0.z; acc.w += w0 * v0.w;
    }
    uint32_t h0, l0, h1, l1;
    if (phase == 0) {
        *(float4*)(g_t1 + (size_t)c * 256 + 4 * t) = acc;
        split2(acc.x, acc.y, h0, l0);
        split2(acc.z, acc.w, h1, l1);
        size_t w = (size_t)c * 128 + 2 * t;
        g_t1ph[w] = h0; g_t1ph[w + 1] = h1;
        g_t1pl[w] = l0; g_t1pl[w + 1] = l1;
    } else {
        float4 v0 = *(const float4*)(xin + (size_t)c * xstride + 4 * t);
        acc.x = 2.f * acc.x - v0.x;
        acc.y = 2.f * acc.y - v0.y;
        acc.z = 2.f * acc.z - v0.z;
        acc.w = 2.f * acc.w - v0.w;
        split2(acc.x, acc.y, h0, l0);
        split2(acc.z, acc.w, h1, l1);
        size_t w = (size_t)c * 128 + 2 * t;
        g_t2ph[w] = h0; g_t2ph[w + 1] = h1;
        g_t2pl[w] = l0; g_t2pl[w + 1] = l1;
    }
}

// ==================== mma.sync bf16 GEMM, cp.async double-buffered ====================
// Grid (157), 512 threads = 16 warps (2 M x 8 N); warp tile 64x32; K-chunk 64.
// SMEM buffer (96KB x2): Ahi 16K | Alo 16K | Bhi 32K | Blo 32K, XOR-16B swizzled 128B rows.
// EPI 0: A = packed [T0|T1|T2], W = g_wch[l]; relu -> g_jk fp32 + g_jkp hi/lo
// EPI 1: A = g_jkp (K=1024), W = g_wcl; +bias, relu, BN, fused [256]->[2] logit -> out
#define BUFSZ 98304u
#define GSM_TOTAL (2 * 98304)

template <int EPI>
__global__ void __launch_bounds__(512)
k_mmagemm(int l, const float* __restrict__ bias, const float* __restrict__ gamma,
          const float* __restrict__ beta, const float* __restrict__ mean,
          const float* __restrict__ var, const float* __restrict__ w2,
          const float* __restrict__ b2, float* __restrict__ out) {
    extern __shared__ char smem[];
    __shared__ float lpart[128][8][2];
    const int K = (EPI == 0) ? KCH : KCL;
    const int Khalf = K >> 1;
    const uint32_t* Bhi = (EPI == 0) ? (g_wch_hi + (size_t)l * 256 * (KCH / 2)) : g_wcl_hi;
    const uint32_t* Blo = (EPI == 0) ? (g_wch_lo + (size_t)l * 256 * (KCH / 2)) : g_wcl_lo;
    const int jkoff = l * 256;

    uint32_t sm = smem_u32(smem);
    int tid = threadIdx.x;
    int wid = tid >> 5, lane = tid & 31;
    int wm = wid >> 3, wn = wid & 7;
    int brow = blockIdx.x * 128;

    float acc[4][4][4];
#pragma unroll
    for (int i = 0; i < 4; i++)
#pragma unroll
        for (int j = 0; j < 4; j++)
#pragma unroll
            for (int q = 0; q < 4; q++) acc[i][j][q] = 0.f;

    int a_mi = lane >> 3;
    int a_row = ((a_mi & 1) << 3) + (lane & 7);
    int a_k8 = a_mi >> 1;                       // 16B-chunk offset 0/1
    int b_nrow = (((lane >> 4) & 1) << 3) + (lane & 7);
    int b_k8 = (lane >> 3) & 1;

    const int nchunks = K >> 6;

    auto stage = [&](int c) {
        uint32_t base = sm + (uint32_t)(c & 1) * BUFSZ;
        uint32_t aHi = base, aLo = base + 16384, bHi = base + 32768, bLo = base + 65536;
        const uint32_t *Ah, *Al;
        int aws, cw;
        if (EPI == 0) {
            int seg = c >> 2, sc = (c & 3) * 32;
            if (seg == 0) {
                if (l == 0) { Ah = g_fph; Al = g_fpl; aws = 128; cw = sc; }
                else { Ah = g_jkph + (size_t)(l - 1) * 128; Al = g_jkpl + (size_t)(l - 1) * 128;
                       aws = 512; cw = sc; }
            } else if (seg == 1) { Ah = g_t1ph; Al = g_t1pl; aws = 128; cw = sc; }
            else                 { Ah = g_t2ph; Al = g_t2pl; aws = 128; cw = sc; }
        } else {
            Ah = g_jkph; Al = g_jkpl; aws = 512; cw = c * 32;
        }
#pragma unroll
        for (int i = 0; i < 2; i++) {
            int idx = tid + i * 512;            // 0..1023
            int r = idx >> 3, ch = idx & 7;
            int gr = brow + r;
            int ok = (gr < NN);
            size_t go = (size_t)(ok ? gr : 0) * aws + cw + ch * 4;
            uint32_t d = (uint32_t)(r * 128) + ((uint32_t)(ch ^ (r & 7)) << 4);
            cpa16(aHi + d, Ah + go, ok ? 16 : 0);
            cpa16(aLo + d, Al + go, ok ? 16 : 0);
        }
#pragma unroll
        for (int i = 0; i < 4; i++) {
            int idx = tid + i * 512;            // 0..2047
            int n = idx >> 3, ch = idx & 7;
            size_t go = (size_t)n * Khalf + c * 32 + ch * 4;
            uint32_t d = (uint32_t)(n * 128) + ((uint32_t)(ch ^ (n & 7)) << 4);
            cpa16(bHi + d, Bhi + go, 16);
            cpa16(bLo + d, Blo + go, 16);
        }
        CP_COMMIT();
    };

    stage(0);
    for (int c = 0; c < nchunks; c++) {
        if (c + 1 < nchunks) { stage(c + 1); CP_WAIT1(); }
        else                 { CP_WAIT0(); }
        __syncthreads();

        uint32_t base = sm + (uint32_t)(c & 1) * BUFSZ;
        uint32_t aHi = base, aLo = base + 16384, bHi = base + 32768, bLo = base + 65536;
#pragma unroll
        for (int kb = 0; kb < 4; kb++) {
            uint32_t ah[4][4], al[4][4], bh[2][4], bl[2][4];
#pragma unroll
            for (int mb = 0; mb < 4; mb++) {
                int row = wm * 64 + mb * 16 + a_row;
                uint32_t off = (uint32_t)(row * 128)
                             + ((uint32_t)((kb * 2 + a_k8) ^ (row & 7)) << 4);
                ldm_x4(ah[mb], aHi + off);
                ldm_x4(al[mb], aLo + off);
            }
#pragma unroll
            for (int np = 0; np < 2; np++) {
                int row = wn * 32 + np * 16 + b_nrow;
                uint32_t off = (uint32_t)(row * 128)
                             + ((uint32_t)((kb * 2 + b_k8) ^ (row & 7)) << 4);
                ldm_x4(bh[np], bHi + off);
                ldm_x4(bl[np], bLo + off);
            }
#pragma unroll
            for (int mb = 0; mb < 4; mb++)
#pragma unroll
                for (int nb = 0; nb < 4; nb++) {
                    int p = nb >> 1, q = (nb & 1) * 2;
                    mma16816(acc[mb][nb], ah[mb], bh[p][q], bh[p][q + 1]);
                    mma16816(acc[mb][nb], al[mb], bh[p][q], bh[p][q + 1]);
                    mma16816(acc[mb][nb], ah[mb], bl[p][q], bl[p][q + 1]);
                }
        }
        __syncthreads();
    }

    int gr_base = brow + wm * 64 + (lane >> 2);
    int cg_base = wn * 32 + (lane & 3) * 2;
    if (EPI == 0) {
#pragma unroll
        for (int mb = 0; mb < 4; mb++) {
#pragma unroll
            for (int nb = 0; nb < 4; nb++) {
                int cg = cg_base + nb * 8;
                int r0 = gr_base + mb * 16;
                int r1 = r0 + 8;
                float* a = acc[mb][nb];
                if (r0 < NN) {
                    float vx = fmaxf(a[0], 0.f), vy = fmaxf(a[1], 0.f);
                    *(float2*)(g_jk + (size_t)r0 * 1024 + jkoff + cg) = make_float2(vx, vy);
                    uint32_t hi, lo;
                    split2(vx, vy, hi, lo);
                    size_t w = (size_t)r0 * 512 + ((jkoff + cg) >> 1);
                    g_jkph[w] = hi;
                    g_jkpl[w] = lo;
                }
                if (r1 < NN) {
                    float vx = fmaxf(a[2], 0.f), vy = fmaxf(a[3], 0.f);
                    *(float2*)(g_jk + (size_t)r1 * 1024 + jkoff + cg) = make_float2(vx, vy);
                    uint32_t hi, lo;
                    split2(vx, vy, hi, lo);
                    size_t w = (size_t)r1 * 512 + ((jkoff + cg) >> 1);
                    g_jkph[w] = hi;
                    g_jkpl[w] = lo;
                }
            }
        }
    } else {
#pragma unroll
        for (int mb = 0; mb < 4; mb++) {
            float p0a = 0.f, p0b = 0.f, p1a = 0.f, p1b = 0.f;
#pragma unroll
            for (int nb = 0; nb < 4; nb++) {
                int cg = cg_base + nb * 8;
                float* a = acc[mb][nb];
                float b0 = bias[cg], b1 = bias[cg + 1];
                float s0 = gamma[cg] * rsqrtf(var[cg] + BN_EPS);
                float s1 = gamma[cg + 1] * rsqrtf(var[cg + 1] + BN_EPS);
                float m0 = mean[cg], m1 = mean[cg + 1];
                float t0 = beta[cg], t1 = beta[cg + 1];
                float w00 = w2[cg * 2], w01 = w2[cg * 2 + 1];
                float w10 = w2[(cg + 1) * 2], w11 = w2[(cg + 1) * 2 + 1];
                float z0x = (fmaxf(a[0] + b0, 0.f) - m0) * s0 + t0;
                float z0y = (fmaxf(a[1] + b1, 0.f) - m1) * s1 + t1;
                float z1x = (fmaxf(a[2] + b0, 0.f) - m0) * s0 + t0;
                float z1y = (fmaxf(a[3] + b1, 0.f) - m1) * s1 + t1;
                p0a += z0x * w00 + z0y * w10;
                p0b += z0x * w01 + z0y * w11;
                p1a += z1x * w00 + z1y * w10;
                p1b += z1x * w01 + z1y * w11;
            }
#pragma unroll
            for (int m = 1; m <= 2; m <<= 1) {
                p0a += __shfl_xor_sync(0xffffffffu, p0a, m);
                p0b += __shfl_xor_sync(0xffffffffu, p0b, m);
                p1a += __shfl_xor_sync(0xffffffffu, p1a, m);
                p1b += __shfl_xor_sync(0xffffffffu, p1b, m);
            }
            if ((lane & 3) == 0) {
                int rl0 = wm * 64 + mb * 16 + (lane >> 2);
                lpart[rl0][wn][0] = p0a;
                lpart[rl0][wn][1] = p0b;
                lpart[rl0 + 8][wn][0] = p1a;
                lpart[rl0 + 8][wn][1] = p1b;
            }
        }
        __syncthreads();
        if (tid < 128) {
            int gr = brow + tid;
            if (gr < NN) {
                float s0 = 0.f, s1 = 0.f;
#pragma unroll
                for (int w = 0; w < 8; w++) {
                    s0 += lpart[tid][w][0];
                    s1 += lpart[tid][w][1];
                }
                out[gr * 2 + 0] = s0 + b2[0];
                out[gr * 2 + 1] = s1 + b2[1];
            }
        }
    }
}

// ==================== launch ====================
extern "C" void kernel_launch(void* const* d_in, const int* in_sizes, int n_in,
                              void* d_out, int out_size) {
    const float* features = (const float*)d_in[0];
    const int*   eidx     = (const int*)d_in[1];
    const float* ew       = (const float*)d_in[3];   // d_in[2] edgenet_input unused (eval)
    const float* cheb_w   = (const float*)d_in[4];
    const float* w1       = (const float*)d_in[5];
    const float* b1       = (const float*)d_in[6];
    const float* gamma    = (const float*)d_in[7];
    const float* beta     = (const float*)d_in[8];
    const float* mean     = (const float*)d_in[9];
    const float* var      = (const float*)d_in[10];
    const float* w2       = (const float*)d_in[11];
    const float* b2       = (const float*)d_in[12];

    const int* row = eidx;
    const int* col = eidx + NE;
    float* out_logit = (float*)d_out;
    float* out_ew    = (float*)d_out + NN * 2;

    cudaFuncSetAttribute(k_mmagemm<0>, cudaFuncAttributeMaxDynamicSharedMemorySize, GSM_TOTAL);
    cudaFuncSetAttribute(k_mmagemm<1>, cudaFuncAttributeMaxDynamicSharedMemorySize, GSM_TOTAL);

    // graph normalization + CSC build
    k_zero<<<(NN + 255) / 256, 256>>>();
    k_deg<<<(NE + 255) / 256, 256>>>(row, ew);
    k_dis<<<(NN + 255) / 256, 256>>>();
    k_norm<<<(NE + 255) / 256, 256>>>(row, col, ew, out_ew);
    k_scan<<<1, 1024>>>();
    k_scatter<<<(NE + 255) / 256, 256>>>(col);
    k_sortfill<<<(NN + 127) / 128, 128>>>(row);

    // operand prep
    {
        int tch = 256 * (KCH / 2);
        for (int l = 0; l < LGC; l++)
            k_prepB<<<(tch + 255) / 256, 256>>>(cheb_w + (size_t)l * 3 * 256 * 256, KCH, 0, l);
        int tcl = 256 * (KCL / 2);
        k_prepB<<<(tcl + 255) / 256, 256>>>(w1, KCL, 1, 0);
        k_prepA<<<(NN * 128 + 255) / 256, 256>>>(features);
    }

    int ggrid = (NN + 127) / 128;  // 157
    for (int l = 0; l < LGC; l++) {
        k_prop<<<(NN + 1) / 2, dim3(64, 2)>>>(features, l, 0);
        k_prop<<<(NN + 1) / 2, dim3(64, 2)>>>(features, l, 1);
        k_mmagemm<0><<<ggrid, 512, GSM_TOTAL>>>(l, nullptr, nullptr, nullptr,
                                                nullptr, nullptr, nullptr, nullptr, nullptr);
    }
    k_mmagemm<1><<<ggrid, 512, GSM_TOTAL>>>(3, b1, gamma, beta, mean, var,
                                            w2, b2, out_logit);
}